// round 10
// baseline (speedup 1.0000x reference)
#include <cuda_runtime.h>

// Problem constants (fixed by the dataset's setup_inputs)
#define L_Q        16
#define D_MODEL    1024
#define H_HEADS    16
#define HD         64
#define BS_TOK     16
#define NB_BLOCKS  1024
#define START_POS  16368
#define T_TOTAL    16384
#define SCALE_F    0.125f   // 1/sqrt(64)

// Attention tiling
#define NC       32          // number of KV chunks (split-KV)
#define CHUNK    512         // tokens per chunk
#define TB       64          // tokens per smem tile
#define NTILES   (CHUNK/TB)  // 8
#define KSTRIDE  68          // K smem row stride floats (16B rows, conflict-free f4)

// dynamic smem layout (floats)
#define SM_KS0   0
#define SM_KS1   (TB * KSTRIDE)
#define SM_VS    (2 * TB * KSTRIDE)
#define SM_PS    (SM_VS + TB * HD)
#define SM_QS    (SM_PS + 16 * TB)
#define SM_MLC   (SM_QS + 16 * HD)
#define ATTN_SMEM_FLOATS (SM_MLC + 64)
#define ATTN_SMEM_BYTES  (ATTN_SMEM_FLOATS * 4)

typedef unsigned long long ull;

// ---------------- f32x2 packed math (ptxas never emits FFMA2 from C++) ----------
__device__ __forceinline__ ull ffma2(ull a, ull b, ull c) {
    ull d;
    asm("fma.rn.f32x2 %0, %1, %2, %3;" : "=l"(d) : "l"(a), "l"(b), "l"(c));
    return d;
}
__device__ __forceinline__ ull fmul2(ull a, ull b) {
    ull d;
    asm("mul.rn.f32x2 %0, %1, %2;" : "=l"(d) : "l"(a), "l"(b));
    return d;
}
__device__ __forceinline__ ull fadd2(ull a, ull b) {
    ull d;
    asm("add.rn.f32x2 %0, %1, %2;" : "=l"(d) : "l"(a), "l"(b));
    return d;
}
__device__ __forceinline__ ull pack2(float x, float y) {
    ull r;
    asm("mov.b64 %0, {%1, %2};" : "=l"(r) : "f"(x), "f"(y));
    return r;
}
__device__ __forceinline__ float2 unpack2(ull v) {
    float x, y;
    asm("mov.b64 {%0, %1}, %2;" : "=f"(x), "=f"(y) : "l"(v));
    return make_float2(x, y);
}

// ---------------- cp.async helpers ----------------
__device__ __forceinline__ void cpa16(unsigned dst, const void* src) {
    asm volatile("cp.async.cg.shared.global [%0], [%1], 16;" :: "r"(dst), "l"(src));
}
#define CP_COMMIT() asm volatile("cp.async.commit_group;" ::: "memory")
#define CP_WAIT(N)  asm volatile("cp.async.wait_group %0;" :: "n"(N) : "memory")

// ---------------- device scratch (no allocations allowed) ----------------
__device__ __align__(16) float g_qkv[L_Q * 3 * D_MODEL];   // [16][3072]
__device__ float g_part[H_HEADS * NC * L_Q * HD];          // per-chunk partial O
__device__ float g_m[H_HEADS * NC * L_Q];                  // per-chunk running max
__device__ float g_s[H_HEADS * NC * L_Q];                  // per-chunk running sumexp
__device__ float g_ao[L_Q * D_MODEL];                      // combined attention output

// block_ids may arrive as int32 (JAX x64-disabled) or int64. Sniff on device.
__device__ __forceinline__ int load_block_id(const void* bi, int blk_idx, int is64) {
    int v;
    if (is64) v = (int)((const long long*)bi)[blk_idx];
    else      v = ((const int*)bi)[blk_idx];
    return v & (NB_BLOCKS - 1);   // memory-safety clamp (no-op for valid ids)
}
__device__ __forceinline__ int sniff_is64(const void* bi) {
    const int* b32 = (const int*)bi;
    return (b32[1] == 0 && b32[3] == 0 && b32[5] == 0 && b32[7] == 0) ? 1 : 0;
}

// base pointers + row stride for one 16-token block
__device__ __forceinline__ void block_base(const float* __restrict__ kp,
                                           const float* __restrict__ vp,
                                           const void* bi, int is64, int bg, int h,
                                           const float*& kb, const float*& vb, int& st) {
    if (bg < (START_POS / BS_TOK)) {
        int blk = load_block_id(bi, bg, is64);
        long long base = (long long)blk * (BS_TOK * H_HEADS * HD) + h * HD;
        kb = kp + base; vb = vp + base; st = H_HEADS * HD;
    } else {
        int l0 = bg * BS_TOK - START_POS;   // 0 (single tail block)
        kb = g_qkv + l0 * (3 * D_MODEL) + D_MODEL     + h * HD;
        vb = g_qkv + l0 * (3 * D_MODEL) + 2 * D_MODEL + h * HD;
        st = 3 * D_MODEL;
    }
}

// ---------------- init: bias-seed qkv and d_out ----------------
__global__ void init_kernel(const float* __restrict__ b_attn,
                            const float* __restrict__ b_proj,
                            float* __restrict__ out) {
    int idx = blockIdx.x * blockDim.x + threadIdx.x;
    if (idx < L_Q * 3 * D_MODEL) g_qkv[idx] = b_attn[idx % (3 * D_MODEL)];
    if (idx < L_Q * D_MODEL)     out[idx]   = b_proj[idx & (D_MODEL - 1)];
}

// ---------------- QKV GEMM: qkv += x @ W_attn (split-K atomics) ----------------
// grid (24, 16): j-tiles of 128, i-chunks of 64. 128 threads.
__global__ void gemm_qkv(const float* __restrict__ x, const float* __restrict__ W) {
    __shared__ float xs[L_Q][64];
    const int tid = threadIdx.x;
    const int i0 = blockIdx.y * 64;
    for (int idx = tid; idx < L_Q * 64; idx += 128) {
        int l = idx >> 6, ii = idx & 63;
        xs[l][ii] = x[l * D_MODEL + i0 + ii];
    }
    __syncthreads();
    const int j = blockIdx.x * 128 + tid;
    float acc[L_Q] = {};
    #pragma unroll 16
    for (int ii = 0; ii < 64; ii++) {
        float w = W[(long)(i0 + ii) * (3 * D_MODEL) + j];
        #pragma unroll
        for (int l = 0; l < L_Q; l++) acc[l] = fmaf(xs[l][ii], w, acc[l]);
    }
    #pragma unroll
    for (int l = 0; l < L_Q; l++) atomicAdd(&g_qkv[l * (3 * D_MODEL) + j], acc[l]);
}

// ---------------- attention partial: cp.async-pipelined split-KV flash decode ----
// grid (NC, H) = 512 CTAs, 256 threads, 3 CTAs/SM.
__global__ __launch_bounds__(256, 3)
void attn_kernel(const float* __restrict__ k_pool,
                 const float* __restrict__ v_pool,
                 const void*  __restrict__ block_ids) {
    extern __shared__ __align__(16) float smem[];
    float* Ks0  = smem + SM_KS0;     // [64][68] buffer 0
    float* Ks1  = smem + SM_KS1;     // [64][68] buffer 1
    float* Vs   = smem + SM_VS;      // [64][64]
    float* Ps   = smem + SM_PS;      // [16][64]
    float* Qs   = smem + SM_QS;      // [16][64] pre-scaled
    float* sm_m = smem + SM_MLC;     // [16]
    float* sm_l = sm_m + 16;         // [16]
    float* sm_c = sm_l + 16;         // [16]

    const int h     = blockIdx.y;
    const int cidx  = blockIdx.x;
    const int cbase = cidx * CHUNK;
    const int tid   = threadIdx.x;
    const int is64  = sniff_is64(block_ids);

    // role decompositions
    const int off = tid >> 4;          // load: row within 16-token block (0..15)
    const int fg  = tid & 15;          // col group
    const int f   = fg << 2;           // float4 column
    const int tok = tid & 63;          // QK: token
    const int qg  = tid >> 6;          // QK: query group (4 queries)
    const int wrp = tid >> 5, lane = tid & 31;
    const int qh  = tid >> 7;          // PV: query half (8 queries)
    const int ts  = (tid >> 4) & 7;    // PV: token slice (8 tokens)

    unsigned ks_u32[2], vs_u32;
    ks_u32[0] = (unsigned)__cvta_generic_to_shared(Ks0);
    ks_u32[1] = (unsigned)__cvta_generic_to_shared(Ks1);
    vs_u32    = (unsigned)__cvta_generic_to_shared(Vs);

    auto issue_K = [&](int tile, int buf) {
        const int nb = (cbase >> 4) + tile * 4;
        #pragma unroll
        for (int k = 0; k < 4; k++) {
            const float *kb, *vb; int st;
            block_base(k_pool, v_pool, block_ids, is64, nb + k, h, kb, vb, st);
            cpa16(ks_u32[buf] + (((k * 16 + off) * KSTRIDE + f) << 2), kb + off * st + f);
        }
    };
    auto issue_V = [&](int tile) {
        const int nb = (cbase >> 4) + tile * 4;
        #pragma unroll
        for (int k = 0; k < 4; k++) {
            const float *kb, *vb; int st;
            block_base(k_pool, v_pool, block_ids, is64, nb + k, h, kb, vb, st);
            cpa16(vs_u32 + (((k * 16 + off) * HD + f) << 2), vb + off * st + f);
        }
    };

    // prologue groups: Ga{K0,V0}, Gb{}, Gc{K1}
    issue_K(0, 0); issue_V(0); CP_COMMIT();
    CP_COMMIT();
    issue_K(1, 1); CP_COMMIT();

    // Q load + stats init (overlaps with async prologue)
    for (int idx = tid; idx < 16 * HD; idx += 256) {
        int l = idx >> 6, j = idx & 63;
        Qs[idx] = g_qkv[l * (3 * D_MODEL) + h * HD + j] * SCALE_F;
    }
    if (tid < 16) { sm_m[tid] = -1e30f; sm_l[tid] = 0.f; sm_c[tid] = 0.f; }

    ull acc[8][2];
    #pragma unroll
    for (int qi = 0; qi < 8; qi++) { acc[qi][0] = pack2(0.f, 0.f); acc[qi][1] = acc[qi][0]; }

    for (int tile = 0; tile < NTILES; tile++) {
        const float* Ksb = (tile & 1) ? Ks1 : Ks0;

        CP_WAIT(2);          // K(tile) (and V0 on tile 0) arrived
        __syncthreads();     // ...and visible block-wide (also covers Ps reuse)

        // ---- QK (FFMA2): thread -> (token, 4 queries) ----
        {
            ull a0 = pack2(0.f, 0.f), a1 = a0, a2 = a0, a3 = a0;
            const ulonglong2* krow = (const ulonglong2*)&Ksb[tok * KSTRIDE];
            const ulonglong2* q0r  = (const ulonglong2*)&Qs[(qg * 4 + 0) * HD];
            const ulonglong2* q1r  = (const ulonglong2*)&Qs[(qg * 4 + 1) * HD];
            const ulonglong2* q2r  = (const ulonglong2*)&Qs[(qg * 4 + 2) * HD];
            const ulonglong2* q3r  = (const ulonglong2*)&Qs[(qg * 4 + 3) * HD];
            #pragma unroll
            for (int j4 = 0; j4 < 16; j4++) {
                ulonglong2 kk = krow[j4];
                ulonglong2 q0 = q0r[j4], q1 = q1r[j4], q2 = q2r[j4], q3 = q3r[j4];
                a0 = ffma2(kk.x, q0.x, ffma2(kk.y, q0.y, a0));
                a1 = ffma2(kk.x, q1.x, ffma2(kk.y, q1.y, a1));
                a2 = ffma2(kk.x, q2.x, ffma2(kk.y, q2.y, a2));
                a3 = ffma2(kk.x, q3.x, ffma2(kk.y, q3.y, a3));
            }
            float2 u0 = unpack2(a0), u1 = unpack2(a1), u2 = unpack2(a2), u3 = unpack2(a3);
            float s0 = u0.x + u0.y, s1 = u1.x + u1.y, s2 = u2.x + u2.y, s3 = u3.x + u3.y;
            const int t0 = cbase + tile * TB;
            const int t  = t0 + tok;
            if (t0 + TB - 1 > START_POS) {   // only last tile of last chunk
                if (t > START_POS + qg * 4 + 0) s0 = -1e30f;
                if (t > START_POS + qg * 4 + 1) s1 = -1e30f;
                if (t > START_POS + qg * 4 + 2) s2 = -1e30f;
                if (t > START_POS + qg * 4 + 3) s3 = -1e30f;
            }
            Ps[(qg * 4 + 0) * TB + tok] = s0;
            Ps[(qg * 4 + 1) * TB + tok] = s1;
            Ps[(qg * 4 + 2) * TB + tok] = s2;
            Ps[(qg * 4 + 3) * TB + tok] = s3;
        }
        // scores for queries 4qg..4qg+3 live entirely in warp-pair (2qg, 2qg+1)
        asm volatile("bar.sync %0, 64;" :: "r"(8 + qg) : "memory");

        // ---- online softmax: warp w handles queries 2w, 2w+1 (within its pair) ----
        #pragma unroll
        for (int qi = 0; qi < 2; qi++) {
            int q = wrp * 2 + qi;
            float v0 = Ps[q * TB + lane];
            float v1 = Ps[q * TB + 32 + lane];
            float mx = fmaxf(v0, v1);
            #pragma unroll
            for (int s = 16; s >= 1; s >>= 1) mx = fmaxf(mx, __shfl_xor_sync(0xffffffffu, mx, s));
            float oldm = sm_m[q];
            float nm = fmaxf(oldm, mx);
            float e0 = __expf(v0 - nm), e1 = __expf(v1 - nm);
            Ps[q * TB + lane]      = e0;
            Ps[q * TB + 32 + lane] = e1;
            float ls = e0 + e1;
            #pragma unroll
            for (int s = 16; s >= 1; s >>= 1) ls += __shfl_xor_sync(0xffffffffu, ls, s);
            if (lane == 0) {
                float cr = __expf(oldm - nm);
                sm_c[q] = cr;
                sm_m[q] = nm;
                sm_l[q] = sm_l[q] * cr + ls;
            }
        }

        CP_WAIT(1);          // V(tile) arrived (K prefetch group may stay in flight)
        __syncthreads();     // V + Ps + sm_c visible block-wide

        // ---- PV (FFMA2): thread -> (8 queries qh*8.., 4 cols f..f+3, tokens ts*8..+7) ----
        {
            #pragma unroll
            for (int qi = 0; qi < 8; qi++) {
                float cr = sm_c[qh * 8 + qi];
                ull crp = pack2(cr, cr);
                acc[qi][0] = fmul2(acc[qi][0], crp);
                acc[qi][1] = fmul2(acc[qi][1], crp);
            }
            #pragma unroll
            for (int g = 0; g < 2; g++) {
                ulonglong2 vj[4];
                #pragma unroll
                for (int j = 0; j < 4; j++)
                    vj[j] = *(const ulonglong2*)&Vs[(ts * 8 + g * 4 + j) * HD + f];
                #pragma unroll
                for (int qi = 0; qi < 8; qi++) {
                    float4 p = *(const float4*)&Ps[(qh * 8 + qi) * TB + ts * 8 + g * 4];
                    ull p0 = pack2(p.x, p.x), p1 = pack2(p.y, p.y);
                    ull p2 = pack2(p.z, p.z), p3 = pack2(p.w, p.w);
                    acc[qi][0] = ffma2(p0, vj[0].x, acc[qi][0]);
                    acc[qi][1] = ffma2(p0, vj[0].y, acc[qi][1]);
                    acc[qi][0] = ffma2(p1, vj[1].x, acc[qi][0]);
                    acc[qi][1] = ffma2(p1, vj[1].y, acc[qi][1]);
                    acc[qi][0] = ffma2(p2, vj[2].x, acc[qi][0]);
                    acc[qi][1] = ffma2(p2, vj[2].y, acc[qi][1]);
                    acc[qi][0] = ffma2(p3, vj[3].x, acc[qi][0]);
                    acc[qi][1] = ffma2(p3, vj[3].y, acc[qi][1]);
                }
            }
        }
        __syncthreads();     // Vs/Ps readers done -> safe to refill

        if (tile + 1 < NTILES) issue_V(tile + 1);
        CP_COMMIT();                                        // gV_tile
        if (tile + 2 < NTILES) issue_K(tile + 2, tile & 1); // into buffer QK just released
        CP_COMMIT();                                        // gK_tile
    }

    // ---- tree-reduce accumulators across the 8 token slices (one-time) ----
    ull* R = (ull*)Ks0;   // reuse: 128 slots x 16 ull = 16KB (no async pending)
    #pragma unroll
    for (int s = 4; s >= 1; s >>= 1) {
        if (ts >= s && ts < 2 * s) {
            int slot = (((ts - s) * 2 + qh) * 16 + fg) * 16;
            #pragma unroll
            for (int qi = 0; qi < 8; qi++) {
                R[slot + qi * 2]     = acc[qi][0];
                R[slot + qi * 2 + 1] = acc[qi][1];
            }
        }
        __syncthreads();
        if (ts < s) {
            int slot = ((ts * 2 + qh) * 16 + fg) * 16;
            #pragma unroll
            for (int qi = 0; qi < 8; qi++) {
                acc[qi][0] = fadd2(acc[qi][0], R[slot + qi * 2]);
                acc[qi][1] = fadd2(acc[qi][1], R[slot + qi * 2 + 1]);
            }
        }
        __syncthreads();
    }

    // ---- write partials ----
    if (ts == 0) {
        const int pbase = (h * NC + cidx) * L_Q;
        #pragma unroll
        for (int qi = 0; qi < 8; qi++) {
            int q = qh * 8 + qi;
            float2 a = unpack2(acc[qi][0]), b = unpack2(acc[qi][1]);
            *(float4*)&g_part[(pbase + q) * HD + f] = make_float4(a.x, a.y, b.x, b.y);
        }
    }
    if (tid < 16) {
        const int pbase = (h * NC + cidx) * L_Q;
        g_m[pbase + tid] = sm_m[tid];
        g_s[pbase + tid] = sm_l[tid];
    }
}

// ---------------- combine split-KV partials ----------------
// grid (H, L), 256 threads: (j = tid&63) x (chunk-group = tid>>6 of 8 chunks)
__global__ void combine_kernel() {
    __shared__ float red[4][64];
    const int h = blockIdx.x;
    const int l = blockIdx.y;
    const int tid = threadIdx.x;
    const int j  = tid & 63;
    const int cg = tid >> 6;

    // all threads compute the 32 merge weights (broadcast loads, L2-hot)
    float m[NC]; float M = -1e30f;
    #pragma unroll
    for (int c = 0; c < NC; c++) { m[c] = g_m[(h * NC + c) * L_Q + l]; M = fmaxf(M, m[c]); }
    float w[NC]; float S = 0.f;
    #pragma unroll
    for (int c = 0; c < NC; c++) {
        w[c] = __expf(m[c] - M);
        S += g_s[(h * NC + c) * L_Q + l] * w[c];
    }

    float acc = 0.f;
    #pragma unroll
    for (int ci = 0; ci < 8; ci++) {
        int c = cg * 8 + ci;
        acc += g_part[((h * NC + c) * L_Q + l) * HD + j] * w[c];
    }
    red[cg][j] = acc;
    __syncthreads();
    if (cg == 0) {
        float tot = red[0][j] + red[1][j] + red[2][j] + red[3][j];
        g_ao[l * D_MODEL + h * HD + j] = tot / S;
    }
}

// ---------------- output projection: out += g_ao @ W_proj (split-K atomics) ----
// grid (8, 16): j-tiles of 128, i-chunks of 64. 128 threads.
__global__ void gemm_proj(const float* __restrict__ W, float* __restrict__ out) {
    __shared__ float as[L_Q][64];
    const int tid = threadIdx.x;
    const int i0 = blockIdx.y * 64;
    for (int idx = tid; idx < L_Q * 64; idx += 128) {
        int l = idx >> 6, ii = idx & 63;
        as[l][ii] = g_ao[l * D_MODEL + i0 + ii];
    }
    __syncthreads();
    const int j = blockIdx.x * 128 + tid;
    float acc[L_Q] = {};
    #pragma unroll 16
    for (int ii = 0; ii < 64; ii++) {
        float w = W[(long)(i0 + ii) * D_MODEL + j];
        #pragma unroll
        for (int l = 0; l < L_Q; l++) acc[l] = fmaf(as[l][ii], w, acc[l]);
    }
    #pragma unroll
    for (int l = 0; l < L_Q; l++) atomicAdd(&out[l * D_MODEL + j], acc[l]);
}

// ---------------- launch ----------------
extern "C" void kernel_launch(void* const* d_in, const int* in_sizes, int n_in,
                              void* d_out, int out_size) {
    const float* x       = (const float*)d_in[0];
    const float* k_pool  = (const float*)d_in[1];
    const float* v_pool  = (const float*)d_in[2];
    const float* W_attn  = (const float*)d_in[3];
    const float* b_attn  = (const float*)d_in[4];
    const float* W_proj  = (const float*)d_in[5];
    const float* b_proj  = (const float*)d_in[6];
    const void*  blk_ids = (const void*)d_in[7];
    float* out = (float*)d_out;

    static int attr_set = 0;
    if (!attr_set) {
        cudaFuncSetAttribute(attn_kernel, cudaFuncAttributeMaxDynamicSharedMemorySize,
                             ATTN_SMEM_BYTES);
        attr_set = 1;
    }

    init_kernel<<<(L_Q * 3 * D_MODEL + 255) / 256, 256>>>(b_attn, b_proj, out);
    gemm_qkv<<<dim3(24, 16), 128>>>(x, W_attn);
    attn_kernel<<<dim3(NC, H_HEADS), 256, ATTN_SMEM_BYTES>>>(k_pool, v_pool, blk_ids);
    combine_kernel<<<dim3(H_HEADS, L_Q), 256>>>();
    gemm_proj<<<dim3(8, 16), 128>>>(W_proj, out);
}

// round 11
// speedup vs baseline: 1.2522x; 1.2522x over previous
#include <cuda_runtime.h>

// Problem constants (fixed by the dataset's setup_inputs)
#define L_Q        16
#define D_MODEL    1024
#define H_HEADS    16
#define HD         64
#define BS_TOK     16
#define NB_BLOCKS  1024
#define START_POS  16368
#define T_TOTAL    16384
#define SCALE_F    0.125f   // 1/sqrt(64)

// Attention tiling
#define NC       16          // number of KV chunks (split-KV)
#define CHUNK    1024        // tokens per chunk
#define TB       128         // tokens per smem tile
#define NTILES   (CHUNK/TB)  // 8
#define KSTRIDE  68          // K smem row stride floats (16B rows, conflict-free f4)

// dynamic smem layout (floats)
#define SM_KS    0
#define SM_VS0   (TB * KSTRIDE)
#define SM_VS1   (SM_VS0 + TB * HD)
#define SM_PS    (SM_VS1 + TB * HD)
#define SM_QS    (SM_PS + 16 * TB)
#define SM_MLC   (SM_QS + 16 * HD)
#define ATTN_SMEM_FLOATS (SM_MLC + 64)
#define ATTN_SMEM_BYTES  (ATTN_SMEM_FLOATS * 4)   // 112,896 B -> 2 CTAs/SM

typedef unsigned long long ull;

// ---------------- f32x2 packed math (ptxas never emits FFMA2 from C++) ----------
__device__ __forceinline__ ull ffma2(ull a, ull b, ull c) {
    ull d;
    asm("fma.rn.f32x2 %0, %1, %2, %3;" : "=l"(d) : "l"(a), "l"(b), "l"(c));
    return d;
}
__device__ __forceinline__ ull fmul2(ull a, ull b) {
    ull d;
    asm("mul.rn.f32x2 %0, %1, %2;" : "=l"(d) : "l"(a), "l"(b));
    return d;
}
__device__ __forceinline__ ull fadd2(ull a, ull b) {
    ull d;
    asm("add.rn.f32x2 %0, %1, %2;" : "=l"(d) : "l"(a), "l"(b));
    return d;
}
__device__ __forceinline__ ull pack2(float x, float y) {
    ull r;
    asm("mov.b64 %0, {%1, %2};" : "=l"(r) : "f"(x), "f"(y));
    return r;
}
__device__ __forceinline__ float2 unpack2(ull v) {
    float x, y;
    asm("mov.b64 {%0, %1}, %2;" : "=f"(x), "=f"(y) : "l"(v));
    return make_float2(x, y);
}

// ---------------- cp.async helpers ----------------
__device__ __forceinline__ void cpa16(unsigned dst, const void* src) {
    asm volatile("cp.async.cg.shared.global [%0], [%1], 16;" :: "r"(dst), "l"(src));
}
#define CP_COMMIT() asm volatile("cp.async.commit_group;" ::: "memory")
#define CP_WAIT(N)  asm volatile("cp.async.wait_group %0;" :: "n"(N) : "memory")

// ---------------- device scratch (no allocations allowed) ----------------
__device__ __align__(16) float g_qkv[L_Q * 3 * D_MODEL];   // [16][3072]
__device__ float g_part[H_HEADS * NC * L_Q * HD];          // per-chunk partial O
__device__ float g_m[H_HEADS * NC * L_Q];                  // per-chunk running max
__device__ float g_s[H_HEADS * NC * L_Q];                  // per-chunk running sumexp
__device__ float g_ao[L_Q * D_MODEL];                      // combined attention output

// block_ids may arrive as int32 (JAX x64-disabled) or int64. Sniff on device.
__device__ __forceinline__ int load_block_id(const void* bi, int blk_idx, int is64) {
    int v;
    if (is64) v = (int)((const long long*)bi)[blk_idx];
    else      v = ((const int*)bi)[blk_idx];
    return v & (NB_BLOCKS - 1);   // memory-safety clamp (no-op for valid ids)
}
__device__ __forceinline__ int sniff_is64(const void* bi) {
    const int* b32 = (const int*)bi;
    return (b32[1] == 0 && b32[3] == 0 && b32[5] == 0 && b32[7] == 0) ? 1 : 0;
}

// base pointers + row stride for one 16-token block
__device__ __forceinline__ void block_base(const float* __restrict__ kp,
                                           const float* __restrict__ vp,
                                           const void* bi, int is64, int bg, int h,
                                           const float*& kb, const float*& vb, int& st) {
    if (bg < (START_POS / BS_TOK)) {
        int blk = load_block_id(bi, bg, is64);
        long long base = (long long)blk * (BS_TOK * H_HEADS * HD) + h * HD;
        kb = kp + base; vb = vp + base; st = H_HEADS * HD;
    } else {
        int l0 = bg * BS_TOK - START_POS;   // 0 (single tail block)
        kb = g_qkv + l0 * (3 * D_MODEL) + D_MODEL     + h * HD;
        vb = g_qkv + l0 * (3 * D_MODEL) + 2 * D_MODEL + h * HD;
        st = 3 * D_MODEL;
    }
}

// ---------------- init: bias-seed qkv and d_out ----------------
__global__ void init_kernel(const float* __restrict__ b_attn,
                            const float* __restrict__ b_proj,
                            float* __restrict__ out) {
    int idx = blockIdx.x * blockDim.x + threadIdx.x;
    if (idx < L_Q * 3 * D_MODEL) g_qkv[idx] = b_attn[idx % (3 * D_MODEL)];
    if (idx < L_Q * D_MODEL)     out[idx]   = b_proj[idx & (D_MODEL - 1)];
}

// ---------------- QKV GEMM: qkv += x @ W_attn (split-K atomics) ----------------
// grid (24, 16): j-tiles of 128, i-chunks of 64. 128 threads.
__global__ void gemm_qkv(const float* __restrict__ x, const float* __restrict__ W) {
    __shared__ float xs[L_Q][64];
    const int tid = threadIdx.x;
    const int i0 = blockIdx.y * 64;
    for (int idx = tid; idx < L_Q * 64; idx += 128) {
        int l = idx >> 6, ii = idx & 63;
        xs[l][ii] = x[l * D_MODEL + i0 + ii];
    }
    __syncthreads();
    const int j = blockIdx.x * 128 + tid;
    float acc[L_Q] = {};
    #pragma unroll 16
    for (int ii = 0; ii < 64; ii++) {
        float w = W[(long)(i0 + ii) * (3 * D_MODEL) + j];
        #pragma unroll
        for (int l = 0; l < L_Q; l++) acc[l] = fmaf(xs[l][ii], w, acc[l]);
    }
    #pragma unroll
    for (int l = 0; l < L_Q; l++) atomicAdd(&g_qkv[l * (3 * D_MODEL) + j], acc[l]);
}

// ---------------- attention partial: cp.async-pipelined split-KV flash decode ----
// grid (NC, H) = 256 CTAs, 256 threads, 2 CTAs/SM.
// TB=128: Q loads and barriers amortized over 2x tokens per phase.
__global__ __launch_bounds__(256, 2)
void attn_kernel(const float* __restrict__ k_pool,
                 const float* __restrict__ v_pool,
                 const void*  __restrict__ block_ids) {
    extern __shared__ __align__(16) float smem[];
    float* Ks   = smem + SM_KS;      // [128][68]
    float* Vs0  = smem + SM_VS0;     // [128][64] buffer 0
    float* Vs1  = smem + SM_VS1;     // [128][64] buffer 1
    float* Ps   = smem + SM_PS;      // [16][128]
    float* Qs   = smem + SM_QS;      // [16][64] pre-scaled
    float* sm_m = smem + SM_MLC;     // [16]
    float* sm_l = sm_m + 16;         // [16]
    float* sm_c = sm_l + 16;         // [16]

    const int h     = blockIdx.y;
    const int cidx  = blockIdx.x;
    const int cbase = cidx * CHUNK;
    const int tid   = threadIdx.x;
    const int is64  = sniff_is64(block_ids);

    // role decompositions
    const int off = tid >> 4;          // load: row within 16-token block (0..15)
    const int fg  = tid & 15;          // col group
    const int f   = fg << 2;           // float4 column
    const int tok = tid & 63;          // QK: token (also tok+64)
    const int qg  = tid >> 6;          // QK: query group (4 queries)
    const int wrp = tid >> 5, lane = tid & 31;
    const int qh  = tid >> 7;          // PV: query half (8 queries)
    const int ts  = (tid >> 4) & 7;    // PV: 16-token slice

    unsigned ks_u32, vs_u32[2];
    ks_u32    = (unsigned)__cvta_generic_to_shared(Ks);
    vs_u32[0] = (unsigned)__cvta_generic_to_shared(Vs0);
    vs_u32[1] = (unsigned)__cvta_generic_to_shared(Vs1);

    // per tile: 8 token-blocks; iteration it is warp-uniform (bg = tile*8+it)
    auto issue_KV = [&](int tile) {
        const int nb = (cbase >> 4) + tile * 8;
        const unsigned vb32 = vs_u32[tile & 1];
        #pragma unroll
        for (int it = 0; it < 8; it++) {
            const float *kb, *vb; int st;
            block_base(k_pool, v_pool, block_ids, is64, nb + it, h, kb, vb, st);
            int tt = it * 16 + off;
            cpa16(ks_u32 + ((tt * KSTRIDE + f) << 2), kb + off * st + f);
            cpa16(vb32   + ((tt * HD + f) << 2),      vb + off * st + f);
        }
    };

    // prologue: tile 0 in flight
    issue_KV(0); CP_COMMIT();

    // Q load + stats init (overlaps with async prologue)
    for (int idx = tid; idx < 16 * HD; idx += 256) {
        int l = idx >> 6, j = idx & 63;
        Qs[idx] = g_qkv[l * (3 * D_MODEL) + h * HD + j] * SCALE_F;
    }
    if (tid < 16) { sm_m[tid] = -1e30f; sm_l[tid] = 0.f; sm_c[tid] = 0.f; }

    ull acc[8][2];
    #pragma unroll
    for (int qi = 0; qi < 8; qi++) { acc[qi][0] = pack2(0.f, 0.f); acc[qi][1] = acc[qi][0]; }

    for (int tile = 0; tile < NTILES; tile++) {
        const float* Vsb = (tile & 1) ? Vs1 : Vs0;

        CP_WAIT(0);          // K(tile) + V(tile) arrived
        __syncthreads();     // visible block-wide; prev tile's Ps/Vs readers done

        // ---- QK (FFMA2): thread -> (2 tokens: tok, tok+64) x (4 queries) ----
        {
            ull aA0 = pack2(0.f, 0.f), aA1 = aA0, aA2 = aA0, aA3 = aA0;
            ull aB0 = aA0, aB1 = aA0, aB2 = aA0, aB3 = aA0;
            const ulonglong2* krowA = (const ulonglong2*)&Ks[tok * KSTRIDE];
            const ulonglong2* krowB = (const ulonglong2*)&Ks[(tok + 64) * KSTRIDE];
            const ulonglong2* q0r   = (const ulonglong2*)&Qs[(qg * 4 + 0) * HD];
            const ulonglong2* q1r   = (const ulonglong2*)&Qs[(qg * 4 + 1) * HD];
            const ulonglong2* q2r   = (const ulonglong2*)&Qs[(qg * 4 + 2) * HD];
            const ulonglong2* q3r   = (const ulonglong2*)&Qs[(qg * 4 + 3) * HD];
            #pragma unroll
            for (int j4 = 0; j4 < 16; j4++) {
                ulonglong2 ka = krowA[j4], kbv = krowB[j4];
                ulonglong2 q0 = q0r[j4], q1 = q1r[j4], q2 = q2r[j4], q3 = q3r[j4];
                aA0 = ffma2(ka.x, q0.x, ffma2(ka.y, q0.y, aA0));
                aA1 = ffma2(ka.x, q1.x, ffma2(ka.y, q1.y, aA1));
                aA2 = ffma2(ka.x, q2.x, ffma2(ka.y, q2.y, aA2));
                aA3 = ffma2(ka.x, q3.x, ffma2(ka.y, q3.y, aA3));
                aB0 = ffma2(kbv.x, q0.x, ffma2(kbv.y, q0.y, aB0));
                aB1 = ffma2(kbv.x, q1.x, ffma2(kbv.y, q1.y, aB1));
                aB2 = ffma2(kbv.x, q2.x, ffma2(kbv.y, q2.y, aB2));
                aB3 = ffma2(kbv.x, q3.x, ffma2(kbv.y, q3.y, aB3));
            }
            float sA[4], sB[4];
            { float2 u; u = unpack2(aA0); sA[0] = u.x + u.y; u = unpack2(aA1); sA[1] = u.x + u.y;
              u = unpack2(aA2); sA[2] = u.x + u.y; u = unpack2(aA3); sA[3] = u.x + u.y;
              u = unpack2(aB0); sB[0] = u.x + u.y; u = unpack2(aB1); sB[1] = u.x + u.y;
              u = unpack2(aB2); sB[2] = u.x + u.y; u = unpack2(aB3); sB[3] = u.x + u.y; }
            const int t0 = cbase + tile * TB;
            if (t0 + TB - 1 > START_POS) {   // only last tile of last chunk
                #pragma unroll
                for (int li = 0; li < 4; li++) {
                    int lim = START_POS + qg * 4 + li;
                    if (t0 + tok      > lim) sA[li] = -1e30f;
                    if (t0 + tok + 64 > lim) sB[li] = -1e30f;
                }
            }
            #pragma unroll
            for (int li = 0; li < 4; li++) {
                Ps[(qg * 4 + li) * TB + tok]      = sA[li];
                Ps[(qg * 4 + li) * TB + tok + 64] = sB[li];
            }
        }
        __syncthreads();     // scores complete; Ks consumed

        // prefetch next tile (in flight across softmax + PV + next QK)
        if (tile + 1 < NTILES) issue_KV(tile + 1);
        CP_COMMIT();

        // ---- online softmax: warp w handles queries 2w, 2w+1 (4 values/lane) ----
        #pragma unroll
        for (int qi = 0; qi < 2; qi++) {
            int q = wrp * 2 + qi;
            float v0 = Ps[q * TB + lane];
            float v1 = Ps[q * TB + 32 + lane];
            float v2 = Ps[q * TB + 64 + lane];
            float v3 = Ps[q * TB + 96 + lane];
            float mx = fmaxf(fmaxf(v0, v1), fmaxf(v2, v3));
            #pragma unroll
            for (int s = 16; s >= 1; s >>= 1) mx = fmaxf(mx, __shfl_xor_sync(0xffffffffu, mx, s));
            float oldm = sm_m[q];
            float nm = fmaxf(oldm, mx);
            float e0 = __expf(v0 - nm), e1 = __expf(v1 - nm);
            float e2 = __expf(v2 - nm), e3 = __expf(v3 - nm);
            Ps[q * TB + lane]      = e0;
            Ps[q * TB + 32 + lane] = e1;
            Ps[q * TB + 64 + lane] = e2;
            Ps[q * TB + 96 + lane] = e3;
            float ls = (e0 + e1) + (e2 + e3);
            #pragma unroll
            for (int s = 16; s >= 1; s >>= 1) ls += __shfl_xor_sync(0xffffffffu, ls, s);
            if (lane == 0) {
                float cr = __expf(oldm - nm);
                sm_c[q] = cr;
                sm_m[q] = nm;
                sm_l[q] = sm_l[q] * cr + ls;
            }
        }
        __syncthreads();     // probs + sm_c visible

        // ---- PV (FFMA2): thread -> (8 queries, 4 cols, 16-token slice ts) ----
        {
            #pragma unroll
            for (int qi = 0; qi < 8; qi++) {
                float cr = sm_c[qh * 8 + qi];
                ull crp = pack2(cr, cr);
                acc[qi][0] = fmul2(acc[qi][0], crp);
                acc[qi][1] = fmul2(acc[qi][1], crp);
            }
            #pragma unroll
            for (int g = 0; g < 4; g++) {
                int tb0 = ts * 16 + g * 4;
                ulonglong2 vj[4];
                #pragma unroll
                for (int j = 0; j < 4; j++)
                    vj[j] = *(const ulonglong2*)&Vsb[(tb0 + j) * HD + f];
                #pragma unroll
                for (int qi = 0; qi < 8; qi++) {
                    float4 p = *(const float4*)&Ps[(qh * 8 + qi) * TB + tb0];
                    ull p0 = pack2(p.x, p.x), p1 = pack2(p.y, p.y);
                    ull p2 = pack2(p.z, p.z), p3 = pack2(p.w, p.w);
                    acc[qi][0] = ffma2(p0, vj[0].x, acc[qi][0]);
                    acc[qi][1] = ffma2(p0, vj[0].y, acc[qi][1]);
                    acc[qi][0] = ffma2(p1, vj[1].x, acc[qi][0]);
                    acc[qi][1] = ffma2(p1, vj[1].y, acc[qi][1]);
                    acc[qi][0] = ffma2(p2, vj[2].x, acc[qi][0]);
                    acc[qi][1] = ffma2(p2, vj[2].y, acc[qi][1]);
                    acc[qi][0] = ffma2(p3, vj[3].x, acc[qi][0]);
                    acc[qi][1] = ffma2(p3, vj[3].y, acc[qi][1]);
                }
            }
        }
    }

    // ---- tree-reduce accumulators across the 8 token slices (one-time) ----
    CP_WAIT(0);
    __syncthreads();
    ull* R = (ull*)Ks;   // reuse: 2048 ull = 16KB <= Ks
    #pragma unroll
    for (int s = 4; s >= 1; s >>= 1) {
        if (ts >= s && ts < 2 * s) {
            int slot = (((ts - s) * 2 + qh) * 16 + fg) * 16;
            #pragma unroll
            for (int qi = 0; qi < 8; qi++) {
                R[slot + qi * 2]     = acc[qi][0];
                R[slot + qi * 2 + 1] = acc[qi][1];
            }
        }
        __syncthreads();
        if (ts < s) {
            int slot = ((ts * 2 + qh) * 16 + fg) * 16;
            #pragma unroll
            for (int qi = 0; qi < 8; qi++) {
                acc[qi][0] = fadd2(acc[qi][0], R[slot + qi * 2]);
                acc[qi][1] = fadd2(acc[qi][1], R[slot + qi * 2 + 1]);
            }
        }
        __syncthreads();
    }

    // ---- write partials ----
    if (ts == 0) {
        const int pbase = (h * NC + cidx) * L_Q;
        #pragma unroll
        for (int qi = 0; qi < 8; qi++) {
            int q = qh * 8 + qi;
            float2 a = unpack2(acc[qi][0]), b = unpack2(acc[qi][1]);
            *(float4*)&g_part[(pbase + q) * HD + f] = make_float4(a.x, a.y, b.x, b.y);
        }
    }
    if (tid < 16) {
        const int pbase = (h * NC + cidx) * L_Q;
        g_m[pbase + tid] = sm_m[tid];
        g_s[pbase + tid] = sm_l[tid];
    }
}

// ---------------- combine split-KV partials ----------------
// grid (H, L), 256 threads: (j = tid&63) x (chunk-group = tid>>6 of 4 chunks)
__global__ void combine_kernel() {
    __shared__ float red[4][64];
    const int h = blockIdx.x;
    const int l = blockIdx.y;
    const int tid = threadIdx.x;
    const int j  = tid & 63;
    const int cg = tid >> 6;

    // all threads compute the 16 merge weights (broadcast loads, L2-hot)
    float m[NC]; float M = -1e30f;
    #pragma unroll
    for (int c = 0; c < NC; c++) { m[c] = g_m[(h * NC + c) * L_Q + l]; M = fmaxf(M, m[c]); }
    float w[NC]; float S = 0.f;
    #pragma unroll
    for (int c = 0; c < NC; c++) {
        w[c] = __expf(m[c] - M);
        S += g_s[(h * NC + c) * L_Q + l] * w[c];
    }

    float acc = 0.f;
    #pragma unroll
    for (int ci = 0; ci < 4; ci++) {
        int c = cg * 4 + ci;
        acc += g_part[((h * NC + c) * L_Q + l) * HD + j] * w[c];
    }
    red[cg][j] = acc;
    __syncthreads();
    if (cg == 0) {
        float tot = red[0][j] + red[1][j] + red[2][j] + red[3][j];
        g_ao[l * D_MODEL + h * HD + j] = tot / S;
    }
}

// ---------------- output projection: out += g_ao @ W_proj (split-K atomics) ----
// grid (8, 16): j-tiles of 128, i-chunks of 64. 128 threads.
__global__ void gemm_proj(const float* __restrict__ W, float* __restrict__ out) {
    __shared__ float as[L_Q][64];
    const int tid = threadIdx.x;
    const int i0 = blockIdx.y * 64;
    for (int idx = tid; idx < L_Q * 64; idx += 128) {
        int l = idx >> 6, ii = idx & 63;
        as[l][ii] = g_ao[l * D_MODEL + i0 + ii];
    }
    __syncthreads();
    const int j = blockIdx.x * 128 + tid;
    float acc[L_Q] = {};
    #pragma unroll 16
    for (int ii = 0; ii < 64; ii++) {
        float w = W[(long)(i0 + ii) * D_MODEL + j];
        #pragma unroll
        for (int l = 0; l < L_Q; l++) acc[l] = fmaf(as[l][ii], w, acc[l]);
    }
    #pragma unroll
    for (int l = 0; l < L_Q; l++) atomicAdd(&out[l * D_MODEL + j], acc[l]);
}

// ---------------- launch ----------------
extern "C" void kernel_launch(void* const* d_in, const int* in_sizes, int n_in,
                              void* d_out, int out_size) {
    const float* x       = (const float*)d_in[0];
    const float* k_pool  = (const float*)d_in[1];
    const float* v_pool  = (const float*)d_in[2];
    const float* W_attn  = (const float*)d_in[3];
    const float* b_attn  = (const float*)d_in[4];
    const float* W_proj  = (const float*)d_in[5];
    const float* b_proj  = (const float*)d_in[6];
    const void*  blk_ids = (const void*)d_in[7];
    float* out = (float*)d_out;

    static int attr_set = 0;
    if (!attr_set) {
        cudaFuncSetAttribute(attn_kernel, cudaFuncAttributeMaxDynamicSharedMemorySize,
                             ATTN_SMEM_BYTES);
        attr_set = 1;
    }

    init_kernel<<<(L_Q * 3 * D_MODEL + 255) / 256, 256>>>(b_attn, b_proj, out);
    gemm_qkv<<<dim3(24, 16), 128>>>(x, W_attn);
    attn_kernel<<<dim3(NC, H_HEADS), 256, ATTN_SMEM_BYTES>>>(k_pool, v_pool, blk_ids);
    combine_kernel<<<dim3(H_HEADS, L_Q), 256>>>();
    gemm_proj<<<dim3(8, 16), 128>>>(W_proj, out);
}